// round 17
// baseline (speedup 1.0000x reference)
#include <cuda_runtime.h>
#include <cuda_bf16.h>
#include <cuda_fp16.h>
#include <cstdint>

// ---------------------------------------------------------------------------
// GCNConv: CSR aggregate (fp16 h, fp32 accum) + bf16x3 HMMA GEMM (M=64, 2 CTA/SM).
// 5 launches: init | histgemm(fused, hist first) | scan12 | fill(4-wide) | gather
// ---------------------------------------------------------------------------

#define MAXN 131072
#define MAXE 2097152
#define C 128

__device__ __align__(16) __half g_hh[(size_t)MAXN * C];     // h = x @ W (fp16)
__device__ __align__(16) __nv_bfloat16 g_wthi[C * C];       // W^T hi limb [n][k]
__device__ __align__(16) __nv_bfloat16 g_wtlo[C * C];       // W^T lo limb [n][k]
__device__ int   g_rowcnt[MAXN];
__device__ int   g_colcnt[MAXN];
__device__ float g_dinv[MAXN];
__device__ int   g_off[MAXN];                               // block-LOCAL excl offsets
__device__ int   g_cursor[MAXN];                            // block-LOCAL cursors
__device__ int   g_blocksum[256];                           // scanned block bases
__device__ unsigned int g_packedc[MAXE];                    // col only (4B/edge)
__device__ int   g_is64;
__device__ int   g_scan_done;

__device__ __forceinline__ int eidx(const void* ei, long long i, int is64) {
    if (is64) return (int)(((const long long*)ei)[i]);
    return ((const int*)ei)[i];
}

// ======================= L1: init (zero + detect + wsplit) ==================
__global__ void __launch_bounds__(256) init_k(const float* __restrict__ W,
                                              const unsigned long long* __restrict__ eu,
                                              int N, int ZB) {
    int b = blockIdx.x;
    if (b < ZB) {
        int i = b * 256 + threadIdx.x;
        if (i < N) { g_rowcnt[i] = 0; g_colcnt[i] = 0; }
        return;
    }
    if (b == ZB) {
        __shared__ int bad;
        if (threadIdx.x == 0) { bad = 0; g_scan_done = 0; }
        __syncthreads();
        if (threadIdx.x < 64) {
            if ((eu[threadIdx.x] >> 32) != 0ULL) atomicAdd(&bad, 1);
        }
        __syncthreads();
        if (threadIdx.x == 0) g_is64 = (bad == 0) ? 1 : 0;
        return;
    }
    // wsplit: 16 blocks
    int b2 = b - ZB - 1;
    __shared__ float tile[32][33];
    int bx = b2 & 3, by = b2 >> 2;
    int tx = threadIdx.x & 31, ty = threadIdx.x >> 5;
    #pragma unroll
    for (int s = 0; s < 4; s++) {
        int k = by * 32 + ty + s * 8;
        int n = bx * 32 + tx;
        tile[ty + s * 8][tx] = W[k * C + n];
    }
    __syncthreads();
    #pragma unroll
    for (int s = 0; s < 4; s++) {
        int n = bx * 32 + ty + s * 8;
        int k = by * 32 + tx;
        float v = tile[tx][ty + s * 8];
        __nv_bfloat16 hi = __float2bfloat16_rn(v);
        __nv_bfloat16 lo = __float2bfloat16_rn(v - __bfloat162float(hi));
        g_wthi[n * C + k] = hi;
        g_wtlo[n * C + k] = lo;
    }
}

// ======================= GEMM config (M=64 tile, 2 CTA/SM) ==================
static constexpr int SM_STRIDE = 136;
static constexpr int SM_XARR = 64 * SM_STRIDE * 2;    // 17408 bytes
static constexpr int SM_WARR = 128 * SM_STRIDE * 2;   // 34816 bytes
static constexpr int SM_XHI = 0;
static constexpr int SM_XLO = SM_XARR;                // 17408
static constexpr int SM_WHI = 2 * SM_XARR;            // 34816
static constexpr int SM_WLO = SM_WHI + SM_WARR;       // 69632
static constexpr int SM_TOTAL = SM_WLO + SM_WARR;     // 104448 bytes
static constexpr int HB = 512;                        // hist blocks (come first)

__device__ __forceinline__ uint32_t smem_u32(const void* p) {
    uint32_t a;
    asm("{ .reg .u64 t; cvta.to.shared.u64 t, %1; cvt.u32.u64 %0, t; }"
        : "=r"(a) : "l"(p));
    return a;
}

#define LDSM_X4(r, addr) \
    asm volatile("ldmatrix.sync.aligned.m8n8.x4.shared.b16 {%0,%1,%2,%3}, [%4];" \
        : "=r"((r)[0]), "=r"((r)[1]), "=r"((r)[2]), "=r"((r)[3]) : "r"(addr))

#define MMA_BF16(c, a, b0, b1) \
    asm volatile("mma.sync.aligned.m16n8k16.row.col.f32.bf16.bf16.f32 " \
        "{%0,%1,%2,%3}, {%4,%5,%6,%7}, {%8,%9}, {%0,%1,%2,%3};" \
        : "+f"((c)[0]), "+f"((c)[1]), "+f"((c)[2]), "+f"((c)[3]) \
        : "r"((a)[0]), "r"((a)[1]), "r"((a)[2]), "r"((a)[3]), "r"(b0), "r"(b1))

// --- hist body: 4-wide edge loads, grid-stride over HB*256 threads ----------
__device__ void hist_body(const void* __restrict__ ei, int E, int hb) {
    int is64 = g_is64;
    int T = HB * 256;
    int t = hb * 256 + threadIdx.x;
    if ((E & 3) == 0) {
        int P = E >> 2;
        if (is64) {
            const longlong2* rp = (const longlong2*)ei;
            const longlong2* cp = (const longlong2*)((const long long*)ei + E);
            for (int p = t; p < P; p += T) {
                longlong2 ra = rp[2 * p], rb = rp[2 * p + 1];
                longlong2 ca = cp[2 * p], cb = cp[2 * p + 1];
                atomicAdd(&g_rowcnt[(int)ra.x], 1);
                atomicAdd(&g_rowcnt[(int)ra.y], 1);
                atomicAdd(&g_rowcnt[(int)rb.x], 1);
                atomicAdd(&g_rowcnt[(int)rb.y], 1);
                atomicAdd(&g_colcnt[(int)ca.x], 1);
                atomicAdd(&g_colcnt[(int)ca.y], 1);
                atomicAdd(&g_colcnt[(int)cb.x], 1);
                atomicAdd(&g_colcnt[(int)cb.y], 1);
            }
        } else {
            const int4* rp = (const int4*)ei;
            const int4* cp = (const int4*)((const int*)ei + E);
            for (int p = t; p < P; p += T) {
                int4 r4 = rp[p], c4 = cp[p];
                atomicAdd(&g_rowcnt[r4.x], 1);
                atomicAdd(&g_rowcnt[r4.y], 1);
                atomicAdd(&g_rowcnt[r4.z], 1);
                atomicAdd(&g_rowcnt[r4.w], 1);
                atomicAdd(&g_colcnt[c4.x], 1);
                atomicAdd(&g_colcnt[c4.y], 1);
                atomicAdd(&g_colcnt[c4.z], 1);
                atomicAdd(&g_colcnt[c4.w], 1);
            }
        }
    } else {
        for (int e = t; e < E; e += T) {
            int r = eidx(ei, e, is64);
            int c = eidx(ei, (long long)E + e, is64);
            atomicAdd(&g_rowcnt[r], 1);
            atomicAdd(&g_colcnt[c], 1);
        }
    }
}

// --- gemm body: bf16x3 mma.sync, 64-row tile ---------------------------------
__device__ void gemm_body(const float* __restrict__ x, int M, int gb, char* sm) {
    int tid = threadIdx.x;
    int wid = tid >> 5;
    int lane = tid & 31;
    int wm = wid >> 2;           // 0..1 -> m offset wm*32
    int wn = wid & 3;            // 0..3 -> n offset wn*32
    int m0 = gb * 64;

    #pragma unroll 4
    for (int idx = tid; idx < 64 * 32; idx += 256) {
        int row = idx >> 5;
        int c4 = idx & 31;
        int gr = m0 + row;
        float4 v = make_float4(0.f, 0.f, 0.f, 0.f);
        if (gr < M) v = *(const float4*)(x + (size_t)gr * C + c4 * 4);
        __nv_bfloat16 hx = __float2bfloat16_rn(v.x);
        __nv_bfloat16 hy = __float2bfloat16_rn(v.y);
        __nv_bfloat16 hz = __float2bfloat16_rn(v.z);
        __nv_bfloat16 hw = __float2bfloat16_rn(v.w);
        __nv_bfloat16 lx = __float2bfloat16_rn(v.x - __bfloat162float(hx));
        __nv_bfloat16 ly = __float2bfloat16_rn(v.y - __bfloat162float(hy));
        __nv_bfloat16 lz = __float2bfloat16_rn(v.z - __bfloat162float(hz));
        __nv_bfloat16 lw = __float2bfloat16_rn(v.w - __bfloat162float(hw));
        size_t off = ((size_t)row * SM_STRIDE + c4 * 4) * 2;
        *(__nv_bfloat162*)(sm + SM_XHI + off)     = __nv_bfloat162(hx, hy);
        *(__nv_bfloat162*)(sm + SM_XHI + off + 4) = __nv_bfloat162(hz, hw);
        *(__nv_bfloat162*)(sm + SM_XLO + off)     = __nv_bfloat162(lx, ly);
        *(__nv_bfloat162*)(sm + SM_XLO + off + 4) = __nv_bfloat162(lz, lw);
    }
    #pragma unroll 4
    for (int idx = tid; idx < 128 * 16; idx += 256) {
        int row = idx >> 4;
        int q = idx & 15;
        size_t soff = ((size_t)row * SM_STRIDE + q * 8) * 2;
        *(uint4*)(sm + SM_WHI + soff) = *(const uint4*)(g_wthi + row * C + q * 8);
        *(uint4*)(sm + SM_WLO + soff) = *(const uint4*)(g_wtlo + row * C + q * 8);
    }
    __syncthreads();

    uint32_t base = smem_u32(sm);
    int sel = lane >> 3;
    int l8 = lane & 7;
    int a_row = l8 + ((sel & 1) << 3);
    int a_kof = (sel >> 1) << 3;
    int b_row = l8 + ((sel >> 1) << 3);
    int b_kof = (sel & 1) << 3;

    uint32_t a_addr[2], b_addr[2];
    #pragma unroll
    for (int i = 0; i < 2; i++)
        a_addr[i] = base + ((uint32_t)((wm * 32 + i * 16 + a_row) * SM_STRIDE + a_kof) << 1);
    #pragma unroll
    for (int j2 = 0; j2 < 2; j2++)
        b_addr[j2] = base + SM_WHI +
                     ((uint32_t)((wn * 32 + j2 * 16 + b_row) * SM_STRIDE + b_kof) << 1);

    float c[2][4][4];
    #pragma unroll
    for (int i = 0; i < 2; i++)
        #pragma unroll
        for (int j = 0; j < 4; j++)
            #pragma unroll
            for (int r = 0; r < 4; r++) c[i][j][r] = 0.f;

    #pragma unroll 1
    for (int ks = 0; ks < 8; ks++) {
        uint32_t ko = (uint32_t)ks * 32;
        uint32_t ahi[2][4], alo[2][4], bhi[2][4], blo[2][4];
        #pragma unroll
        for (int i = 0; i < 2; i++) {
            LDSM_X4(ahi[i], a_addr[i] + ko);
            LDSM_X4(alo[i], a_addr[i] + ko + SM_XARR);
        }
        #pragma unroll
        for (int j2 = 0; j2 < 2; j2++) {
            LDSM_X4(bhi[j2], b_addr[j2] + ko);
            LDSM_X4(blo[j2], b_addr[j2] + ko + SM_WARR);
        }
        #pragma unroll
        for (int i = 0; i < 2; i++) {
            #pragma unroll
            for (int j = 0; j < 4; j++) {
                int j2 = j >> 1;
                int rb = (j & 1) << 1;
                MMA_BF16(c[i][j], ahi[i], bhi[j2][rb], bhi[j2][rb + 1]);
                MMA_BF16(c[i][j], ahi[i], blo[j2][rb], blo[j2][rb + 1]);
                MMA_BF16(c[i][j], alo[i], bhi[j2][rb], bhi[j2][rb + 1]);
            }
        }
    }

    int g = lane >> 2;
    int tg = lane & 3;
    #pragma unroll
    for (int i = 0; i < 2; i++) {
        int row0 = m0 + wm * 32 + i * 16 + g;
        #pragma unroll
        for (int j = 0; j < 4; j++) {
            int col = wn * 32 + j * 8 + tg * 2;
            if (row0 < M) {
                __half2 v01 = __floats2half2_rn(c[i][j][0], c[i][j][1]);
                *(__half2*)(g_hh + (size_t)row0 * C + col) = v01;
            }
            if (row0 + 8 < M) {
                __half2 v23 = __floats2half2_rn(c[i][j][2], c[i][j][3]);
                *(__half2*)(g_hh + (size_t)(row0 + 8) * C + col) = v23;
            }
        }
    }
}

// ======================= L2: fused hist + gemm ==============================
__global__ void __launch_bounds__(256, 2) histgemm_k(const float* __restrict__ x,
                                                     const void* __restrict__ ei,
                                                     int M, int E) {
    extern __shared__ char sm[];
    int b = blockIdx.x;
    if (b < HB) hist_body(ei, E, b);
    else        gemm_body(x, M, b - HB, sm);
}

// ======== L3: scan1 + dinv + cursor init + PARALLEL tail scan ===============
__global__ void __launch_bounds__(1024) scan12_k(int N, int nb) {
    __shared__ int s[1024];
    __shared__ int flag;
    __shared__ int bs[128];
    int i = blockIdx.x * 1024 + threadIdx.x;
    int v = (i < N) ? g_rowcnt[i] : 0;
    s[threadIdx.x] = v;
    __syncthreads();
    #pragma unroll
    for (int off = 1; off < 1024; off <<= 1) {
        int t = (threadIdx.x >= off) ? s[threadIdx.x - off] : 0;
        __syncthreads();
        s[threadIdx.x] += t;
        __syncthreads();
    }
    if (i < N) {
        int local = s[threadIdx.x] - v;
        g_off[i] = local;
        g_cursor[i] = local;
        g_dinv[i] = rsqrtf((float)(g_colcnt[i] + 1));
    }
    if (threadIdx.x == 1023) {
        g_blocksum[blockIdx.x] = s[1023];
        __threadfence();
    }
    __syncthreads();
    if (threadIdx.x == 0) {
        int t = atomicAdd(&g_scan_done, 1);
        flag = (t == nb - 1) ? 1 : 0;
    }
    __syncthreads();
    if (flag) {
        int t = threadIdx.x;
        if (t < 128) bs[t] = (t < nb) ? g_blocksum[t] : 0;
        __syncthreads();
        #pragma unroll
        for (int off = 1; off < 128; off <<= 1) {
            int vv = (t >= off && t < 128) ? bs[t - off] : 0;
            __syncthreads();
            if (t < 128) bs[t] += vv;
            __syncthreads();
        }
        if (t < nb) g_blocksum[t] = (t == 0) ? 0 : bs[t - 1];
    }
}

// ======================= L4: fill (4-wide, block base on fly) ===============
__global__ void fill_k(const void* __restrict__ ei, int E) {
    int is64 = g_is64;
    int T = gridDim.x * blockDim.x;
    int t = blockIdx.x * blockDim.x + threadIdx.x;
    if ((E & 3) == 0) {
        int P = E >> 2;
        if (is64) {
            const longlong2* rp = (const longlong2*)ei;
            const longlong2* cp = (const longlong2*)((const long long*)ei + E);
            for (int p = t; p < P; p += T) {
                longlong2 ra = rp[2 * p], rb = rp[2 * p + 1];
                longlong2 ca = cp[2 * p], cb = cp[2 * p + 1];
                int r0 = (int)ra.x, r1 = (int)ra.y, r2 = (int)rb.x, r3 = (int)rb.y;
                int pos0 = atomicAdd(&g_cursor[r0], 1) + g_blocksum[r0 >> 10];
                int pos1 = atomicAdd(&g_cursor[r1], 1) + g_blocksum[r1 >> 10];
                int pos2 = atomicAdd(&g_cursor[r2], 1) + g_blocksum[r2 >> 10];
                int pos3 = atomicAdd(&g_cursor[r3], 1) + g_blocksum[r3 >> 10];
                g_packedc[pos0] = (unsigned int)(long long)ca.x;
                g_packedc[pos1] = (unsigned int)(long long)ca.y;
                g_packedc[pos2] = (unsigned int)(long long)cb.x;
                g_packedc[pos3] = (unsigned int)(long long)cb.y;
            }
        } else {
            const int4* rp = (const int4*)ei;
            const int4* cp = (const int4*)((const int*)ei + E);
            for (int p = t; p < P; p += T) {
                int4 r4 = rp[p], c4 = cp[p];
                int pos0 = atomicAdd(&g_cursor[r4.x], 1) + g_blocksum[r4.x >> 10];
                int pos1 = atomicAdd(&g_cursor[r4.y], 1) + g_blocksum[r4.y >> 10];
                int pos2 = atomicAdd(&g_cursor[r4.z], 1) + g_blocksum[r4.z >> 10];
                int pos3 = atomicAdd(&g_cursor[r4.w], 1) + g_blocksum[r4.w >> 10];
                g_packedc[pos0] = (unsigned int)c4.x;
                g_packedc[pos1] = (unsigned int)c4.y;
                g_packedc[pos2] = (unsigned int)c4.z;
                g_packedc[pos3] = (unsigned int)c4.w;
            }
        }
    } else {
        for (int e = t; e < E; e += T) {
            int r = eidx(ei, e, is64);
            int c = eidx(ei, (long long)E + e, is64);
            int pos = atomicAdd(&g_cursor[r], 1) + g_blocksum[r >> 10];
            g_packedc[pos] = (unsigned int)c;
        }
    }
}

// ======================= L5: gather (4-wide pipelined, half-warp/node) ======
__global__ void gather_k(uint4* __restrict__ out, int N) {
    int gt = blockIdx.x * blockDim.x + threadIdx.x;
    int n = gt >> 4;                 // half-warp per node
    int l16 = gt & 15;               // 16 lanes x 16B = 256B fp16 row
    if (n >= N) return;

    int beg = g_off[n] + g_blocksum[n >> 10];
    int end = beg + g_rowcnt[n];
    float d = g_dinv[n];
    float s = d * d;

    const uint4* h4 = (const uint4*)g_hh;
    uint4 raw = h4[((size_t)n << 4) + l16];
    float2 f0 = __half22float2(*(__half2*)&raw.x);
    float2 f1 = __half22float2(*(__half2*)&raw.y);
    float2 f2 = __half22float2(*(__half2*)&raw.z);
    float2 f3 = __half22float2(*(__half2*)&raw.w);
    float a0 = s * f0.x, a1 = s * f0.y, a2 = s * f1.x, a3 = s * f1.y;
    float a4 = s * f2.x, a5 = s * f2.y, a6 = s * f3.x, a7 = s * f3.y;

#define ACC8(vv, nn) { \
        float2 t0 = __half22float2(*(__half2*)&(vv).x); \
        float2 t1 = __half22float2(*(__half2*)&(vv).y); \
        float2 t2 = __half22float2(*(__half2*)&(vv).z); \
        float2 t3 = __half22float2(*(__half2*)&(vv).w); \
        a0 += (nn) * t0.x; a1 += (nn) * t0.y; \
        a2 += (nn) * t1.x; a3 += (nn) * t1.y; \
        a4 += (nn) * t2.x; a5 += (nn) * t2.y; \
        a6 += (nn) * t3.x; a7 += (nn) * t3.y; }

    int j = beg;
    for (; j + 4 <= end; j += 4) {
        int c0 = (int)g_packedc[j];
        int c1 = (int)g_packedc[j + 1];
        int c2 = (int)g_packedc[j + 2];
        int c3 = (int)g_packedc[j + 3];
        float n0 = d * g_dinv[c0];
        float n1 = d * g_dinv[c1];
        float n2 = d * g_dinv[c2];
        float n3 = d * g_dinv[c3];
        uint4 v0 = h4[((size_t)c0 << 4) + l16];
        uint4 v1 = h4[((size_t)c1 << 4) + l16];
        uint4 v2 = h4[((size_t)c2 << 4) + l16];
        uint4 v3 = h4[((size_t)c3 << 4) + l16];
        ACC8(v0, n0); ACC8(v1, n1); ACC8(v2, n2); ACC8(v3, n3);
    }
    for (; j < end; j++) {
        int cc = (int)g_packedc[j];
        float norm = d * g_dinv[cc];
        uint4 rv = h4[((size_t)cc << 4) + l16];
        ACC8(rv, norm);
    }
#undef ACC8
    float4 lo = make_float4(a0, a1, a2, a3);
    float4 hi = make_float4(a4, a5, a6, a7);
    float4* op = (float4*)out;
    op[((size_t)n << 5) + l16 * 2]     = lo;
    op[((size_t)n << 5) + l16 * 2 + 1] = hi;
}

// ---------------------------------------------------------------------------
extern "C" void kernel_launch(void* const* d_in, const int* in_sizes, int n_in,
                              void* d_out, int out_size) {
    const float* x = (const float*)d_in[0];
    const float* W = (const float*)d_in[1];
    const void*  ei = d_in[2];

    int N = in_sizes[0] / C;
    int E = in_sizes[2] / 2;

    cudaFuncSetAttribute(histgemm_k, cudaFuncAttributeMaxDynamicSharedMemorySize,
                         SM_TOTAL);

    int ZB = (N + 255) / 256;
    init_k<<<ZB + 17, 256>>>(W, (const unsigned long long*)ei, N, ZB);

    int G = (N + 63) / 64;
    histgemm_k<<<HB + G, 256, SM_TOTAL>>>(x, ei, N, E);

    int nb = (N + 1023) / 1024;
    scan12_k<<<nb, 1024>>>(N, nb);

    fill_k<<<1024, 256>>>(ei, E);

    long long gt = (long long)N * 16;
    gather_k<<<(int)((gt + 255) / 256), 256>>>((uint4*)d_out, N);
}